// round 12
// baseline (speedup 1.0000x reference)
#include <cuda_runtime.h>

#define NPED    4096
#define NBLK    1024
#define NTHR    256
#define TILE    2048          // float2 per smem tile (16KB)
#define PPB     4             // pedestrians per block (2 warps each)

#define DT        0.4f
#define K_ATTR    2.0f
#define PED_SPEED 1.0f
#define INV_MASS  (1.0f/60.0f)
#define EPS       1e-8f
#define A_COST    5.0f
#define B_COST    2.0f
// 10*exp((0.6-dist)/0.71) = exp2(C1 - dist*C2)
#define C2_EXP 2.0319648f
#define C1_EXP 4.5411053f

__device__ unsigned int g_ticket = 0;       // reset by last block each launch
__device__ float g_dev_part[NBLK];

__device__ __forceinline__ float ex2_approx(float x) {
    float r; asm("ex2.approx.f32 %0, %1;" : "=f"(r) : "f"(x)); return r;
}
__device__ __forceinline__ float rsqrt_approx(float x) {
    float r; asm("rsqrt.approx.f32 %0, %1;" : "=f"(r) : "f"(x)); return r;
}

// Fused kernel: stacked copy + forces + propagation + cost.
// 1024 blocks x 256 threads. Block b owns peds i = b*4 + (w>>1); warp's
// half h = w&1 covers half of each j-tile. Two 16KB tiles cover all j.
__global__ void __launch_bounds__(NTHR) fused_kernel(
    const float* __restrict__ state,       // [N,4]
    const float* __restrict__ goal,        // [N,2]
    const float* __restrict__ stacked_in,  // [N*4]
    const float* __restrict__ observed,    // [N,4]
    const float* __restrict__ cost_in,     // [1]
    float* __restrict__ out_state,         // [N,4]
    float* __restrict__ out_cost,          // [1]
    float* __restrict__ out_stacked)       // [2*N*4] (4B-aligned only)
{
    __shared__ float2 spos[TILE];          // 16KB
    __shared__ float2 s_f[8];              // per-warp force partials
    __shared__ float  s_dev[PPB];
    __shared__ int    s_last;
    __shared__ float  s_red[16];

    const int tid  = threadIdx.x;
    const int lane = tid & 31;
    const int w    = tid >> 5;
    const int p    = w >> 1;               // local ped index 0..3
    const int h    = w & 1;                // j-half within each tile
    const int i    = blockIdx.x * PPB + p;

    // fused concat copy: g in [0, 16384) -> blocks 0..63 cover both halves
    {
        int g = blockIdx.x * NTHR + tid;
        if (g < NPED * 4) {
            out_stacked[g]            = stacked_in[g];
            out_stacked[NPED * 4 + g] = state[g];
        }
    }

    const float4 si = ((const float4*)state)[i];
    const float xi = si.x, yi = si.y;

    float fx = 0.0f, fy = 0.0f;

    const float2* __restrict__ pos2 = (const float2*)state;  // row = {pos, vel}

    #pragma unroll
    for (int t = 0; t < NPED / TILE; t++) {
        #pragma unroll
        for (int k = tid; k < TILE; k += NTHR)
            spos[k] = pos2[(t * TILE + k) * 2];
        __syncthreads();

        const int jbeg = h * (TILE / 2) + lane;
        const int jend = (h + 1) * (TILE / 2);
        #pragma unroll 8
        for (int jj = jbeg; jj < jend; jj += 32) {
            float2 pj = spos[jj];
            float dx = xi - pj.x;
            float dy = yi - pj.y;
            float d2 = fmaf(dx, dx, fmaf(dy, dy, EPS));
            float rd = rsqrt_approx(d2);
            float dist = d2 * rd;                                 // sqrt(d2)
            float coef = ex2_approx(fmaf(dist, -C2_EXP, C1_EXP)) * rd;
            // j==i: dx=dy=0 exactly -> contributes exactly 0
            fx = fmaf(coef, dx, fx);
            fy = fmaf(coef, dy, fy);
        }
        __syncthreads();
    }

    // warp reduction
    #pragma unroll
    for (int o = 16; o > 0; o >>= 1) {
        fx += __shfl_xor_sync(0xffffffffu, fx, o);
        fy += __shfl_xor_sync(0xffffffffu, fy, o);
    }
    if (lane == 0) s_f[w] = make_float2(fx, fy);
    __syncthreads();

    // threads 0..3 finalize one pedestrian each
    if (tid < PPB) {
        const int pi = blockIdx.x * PPB + tid;
        const float4 sr = ((const float4*)state)[pi];
        const float pxi = sr.x, pyi = sr.y, vx = sr.z, vy = sr.w;

        float tfx = s_f[2*tid].x + s_f[2*tid + 1].x;   // fixed order: deterministic
        float tfy = s_f[2*tid].y + s_f[2*tid + 1].y;

        const float2 gl = ((const float2*)goal)[pi];
        float tgx = gl.x - pxi, tgy = gl.y - pyi;
        float dg2 = fmaf(tgx, tgx, fmaf(tgy, tgy, EPS));
        float rdg = rsqrt_approx(dg2);
        float afx = K_ATTR * fmaf(PED_SPEED * tgx, rdg, -vx);
        float afy = K_ATTR * fmaf(PED_SPEED * tgy, rdg, -vy);

        float Fx = fmaf(tfx, INV_MASS, afx);
        float Fy = fmaf(tfy, INV_MASS, afy);

        float npx = pxi + vx * DT + 0.5f * Fx * (DT * DT);
        float npy = pyi + vy * DT + 0.5f * Fy * (DT * DT);
        float nvx = fmaf(Fx, DT, vx);
        float nvy = fmaf(Fy, DT, vy);
        float spd = sqrtf(fmaf(nvx, nvx, fmaf(nvy, nvy, EPS)));
        float scale = fminf(1.0f, PED_SPEED / spd);

        ((float4*)out_state)[pi] = make_float4(npx, npy, nvx * scale, nvy * scale);

        // local deviation contribution (peds = rows 1..N-1)
        float dev = 0.0f;
        if (pi > 0) {
            float ox = observed[pi*4 + 0];
            float oy = observed[pi*4 + 1];
            float ddx = npx - ox, ddy = npy - oy;
            dev = sqrtf(fmaf(ddx, ddx, fmaf(ddy, ddy, EPS)));
        }
        s_dev[tid] = dev;
    }
    __syncthreads();

    if (tid == 0) {
        float d = 0.0f;
        #pragma unroll
        for (int k = 0; k < PPB; k++) d += s_dev[k];
        g_dev_part[blockIdx.x] = d;
    }

    // make this block's global writes visible, then take a ticket
    __threadfence();
    if (tid == 0) {
        unsigned int t = atomicAdd(&g_ticket, 1u);
        s_last = (t == NBLK - 1) ? 1 : 0;
    }
    __syncthreads();

    // ---- last block finalizes the cost ----
    if (s_last) {
        __threadfence();
        const float rx = __ldcg(&out_state[0]);
        const float ry = __ldcg(&out_state[1]);

        // deterministic sum of per-block deviation partials
        float dev = 0.0f;
        #pragma unroll
        for (int k = 0; k < NBLK / NTHR; k++)
            dev += __ldcg(&g_dev_part[tid + k * NTHR]);

        // blame over peds 1..N-1
        float blm = 0.0f;
        for (int pp = 1 + tid; pp < NPED; pp += NTHR) {
            float2 q = __ldcg((const float2*)(out_state + pp * 4));
            float bx = q.x - rx, by = q.y - ry;
            float d = sqrtf(fmaf(bx, bx, fmaf(by, by, EPS)));
            blm += ex2_approx(-d * 1.4426950f);   // exp(-d), E_COST=1
        }

        #pragma unroll
        for (int o = 16; o > 0; o >>= 1) {
            dev += __shfl_xor_sync(0xffffffffu, dev, o);
            blm += __shfl_xor_sync(0xffffffffu, blm, o);
        }
        if (lane == 0) { s_red[w] = dev; s_red[8 + w] = blm; }
        __syncthreads();

        if (tid == 0) {
            float devt = 0.0f, blmt = 0.0f;
            #pragma unroll
            for (int k = 0; k < 8; k++) { devt += s_red[k]; blmt += s_red[8 + k]; }
            float ix = state[0], iy = state[1];
            float gx = goal[0],  gy = goal[1];
            float d1x = ix - gx, d1y = iy - gy;
            float d2x = rx - gx, d2y = ry - gy;
            float pg = sqrtf(fmaf(d1x, d1x, fmaf(d1y, d1y, EPS)))
                     - sqrtf(fmaf(d2x, d2x, fmaf(d2y, d2y, EPS)));
            out_cost[0] = cost_in[0] + A_COST * devt + B_COST * blmt - pg;
            g_ticket = 0;   // reset for next graph replay
            __threadfence();
        }
    }
}

extern "C" void kernel_launch(void* const* d_in, const int* in_sizes, int n_in,
                              void* d_out, int out_size) {
    const float* state      = (const float*)d_in[0];
    const float* cost_in    = (const float*)d_in[1];
    const float* stacked_in = (const float*)d_in[2];
    const float* goal       = (const float*)d_in[3];
    const float* observed   = (const float*)d_in[4];

    float* out = (float*)d_out;
    float* out_state   = out;
    float* out_cost    = out + NPED*4;
    float* out_stacked = out + NPED*4 + 1;

    fused_kernel<<<NBLK, NTHR>>>(state, goal, stacked_in, observed, cost_in,
                                 out_state, out_cost, out_stacked);
}